// round 4
// baseline (speedup 1.0000x reference)
#include <cuda_runtime.h>
#include <math.h>

#define CC 32
#define HH 256
#define WW 256
#define TW 64           // tile width
#define RB 2            // output rows per block
#define SR (RB + 2)     // staged rows
#define TWP (TW + 2)    // staged row width (halo)
#define NT (TW * RB)    // threads per block = 128
#define KP 9
#define EPSF 1e-12f

__global__ __launch_bounds__(NT) void asfr_kernel(
    const float* __restrict__ fe,
    const float* __restrict__ fu,
    float* __restrict__ out)
{
    __shared__ float sm[CC * SR * TWP];   // 32*4*66*4 = 33,792 bytes

    const int w0 = blockIdx.x * TW;
    const int h0 = blockIdx.y * RB;
    const int b  = blockIdx.z;
    const int tid = threadIdx.x;
    const int ty  = tid >> 6;      // 0..RB-1
    const int tx  = tid & (TW - 1);

    // ---- division-free cooperative staging of 4 rows x 32 ch x 66 cols ----
    const float* fub = fu + (size_t)b * CC * HH * WW;
#pragma unroll 2
    for (int c = 0; c < CC; c++) {
#pragma unroll
        for (int dd = 0; dd < SR / RB; dd++) {
            const int dy = dd * RB + ty;          // 0..3
            const int gy = h0 - 1 + dy;
            const bool yok = (gy >= 0) && (gy < HH);
            const float* row = fub + ((size_t)c * HH + gy) * WW;
            float* srow = sm + (c * SR + dy) * TWP;
            float v = yok ? row[w0 + tx] : 0.0f;  // gx = w0+tx always < WW
            srow[tx + 1] = v;
            if (tx == 0)
                srow[0] = (yok && w0 > 0) ? row[w0 - 1] : 0.0f;
            if (tx == TW - 1)
                srow[TW + 1] = (yok && (w0 + TW) < WW) ? row[w0 + TW] : 0.0f;
        }
    }
    __syncthreads();

    const int h = h0 + ty;
    const int w = w0 + tx;
    const float* feb = fe + (((size_t)b * CC) * HH + h) * WW + w;

    // ---- pass 1: per-k dot(p,f) and ||p||^2, plus ||f||^2 ----
    float dot[KP], pn2[KP];
#pragma unroll
    for (int k = 0; k < KP; k++) { dot[k] = 0.0f; pn2[k] = 0.0f; }
    float fn2 = 0.0f;

#pragma unroll 4
    for (int c = 0; c < CC; c++) {
        float f = feb[(size_t)c * HH * WW];
        fn2 = fmaf(f, f, fn2);
        const float* s = sm + (c * SR + ty) * TWP + tx;
#pragma unroll
        for (int dy = 0; dy < 3; dy++) {
#pragma unroll
            for (int dx = 0; dx < 3; dx++) {
                float p = s[dy * TWP + dx];
                int k = dy * 3 + dx;
                dot[k] = fmaf(p, f, dot[k]);
                pn2[k] = fmaf(p, p, pn2[k]);
            }
        }
    }

    // ---- weights: 0.5*softmax(cos) + 0.5*softmax(-dist) ----
    float fn = fmaxf(sqrtf(fn2), EPSF);
    float cs[KP], ed[KP];
    float cmax = -1e30f, emax = -1e30f;
#pragma unroll
    for (int k = 0; k < KP; k++) {
        float pn = fmaxf(sqrtf(pn2[k]), EPSF);
        float c  = dot[k] / (pn * fn);
        float d2 = pn2[k] + fn2 - 2.0f * dot[k];
        float e  = -sqrtf(fmaxf(d2, 0.0f));
        cs[k] = c; ed[k] = e;
        cmax = fmaxf(cmax, c);
        emax = fmaxf(emax, e);
    }
    float csum = 0.0f, esum = 0.0f;
#pragma unroll
    for (int k = 0; k < KP; k++) {
        cs[k] = __expf(cs[k] - cmax); csum += cs[k];
        ed[k] = __expf(ed[k] - emax); esum += ed[k];
    }
    float ci = 0.5f / csum, ei = 0.5f / esum;
    float wgt[KP];
#pragma unroll
    for (int k = 0; k < KP; k++) wgt[k] = cs[k] * ci + ed[k] * ei;

    // ---- pass 2: refined = sum_k w_k * p_k ; out = refined + fe ----
    float* ob = out + (((size_t)b * CC) * HH + h) * WW + w;
#pragma unroll 4
    for (int c = 0; c < CC; c++) {
        float f = feb[(size_t)c * HH * WW];   // L1 hit from pass 1
        const float* s = sm + (c * SR + ty) * TWP + tx;
        float r = 0.0f;
#pragma unroll
        for (int dy = 0; dy < 3; dy++) {
#pragma unroll
            for (int dx = 0; dx < 3; dx++) {
                r = fmaf(wgt[dy * 3 + dx], s[dy * TWP + dx], r);
            }
        }
        ob[(size_t)c * HH * WW] = r + f;
    }
}

extern "C" void kernel_launch(void* const* d_in, const int* in_sizes, int n_in,
                              void* d_out, int out_size)
{
    (void)in_sizes; (void)n_in; (void)out_size;
    const float* fe = (const float*)d_in[0];
    const float* fu = (const float*)d_in[1];
    float* out = (float*)d_out;

    dim3 grid(WW / TW, HH / RB, 4);
    asfr_kernel<<<grid, NT>>>(fe, fu, out);
}

// round 5
// speedup vs baseline: 2.5271x; 2.5271x over previous
#include <cuda_runtime.h>
#include <math.h>

#define CC 32
#define HH 256
#define WW 256
#define KP 9
#define EPSF 1e-12f
#define SEGW 30                // output pixels per warp
#define NSEG ((WW + SEGW - 1) / SEGW)   // 9
#define WPB 8                  // warps per block
#define NT (WPB * 32)
#define HW (HH * WW)

__global__ __launch_bounds__(NT) void asfr_kernel(
    const float* __restrict__ fe,
    const float* __restrict__ fu,
    float* __restrict__ out)
{
    const unsigned FULL = 0xffffffffu;
    const int lane = threadIdx.x & 31;
    const int wid  = threadIdx.x >> 5;
    const int seg  = blockIdx.x;
    const int h    = blockIdx.y * WPB + wid;
    const int b    = blockIdx.z;

    const int gx   = seg * SEGW - 1 + lane;          // [-1 .. 270]
    const bool xok = (gx >= 0) && (gx < WW);
    const bool y0  = (h > 0);
    const bool y2  = (h < HH - 1);
    const int gxc  = min(max(gx, 0), WW - 1);        // safe address

    const float* fup = fu + (((size_t)b * CC) * HH + h) * WW + gxc;
    const float* fep = fe + (((size_t)b * CC) * HH + h) * WW + gxc;

    // ---- pass 1: accumulate dot(p,f), ||p||^2 per k, and ||f||^2 ----
    float dot[KP], pn2[KP];
#pragma unroll
    for (int k = 0; k < KP; k++) { dot[k] = 0.0f; pn2[k] = 0.0f; }
    float fn2 = 0.0f;

#pragma unroll 4
    for (int c = 0; c < CC; c++) {
        const float* p = fup + (size_t)c * HW;
        float vt = (xok && y0) ? p[-WW] : 0.0f;
        float vm =  xok        ? p[0]   : 0.0f;
        float vb = (xok && y2) ? p[WW]  : 0.0f;
        float f  =  xok        ? fep[(size_t)c * HW] : 0.0f;

        float lt = __shfl_up_sync(FULL, vt, 1);
        float rt = __shfl_down_sync(FULL, vt, 1);
        float lm = __shfl_up_sync(FULL, vm, 1);
        float rm = __shfl_down_sync(FULL, vm, 1);
        float lb = __shfl_up_sync(FULL, vb, 1);
        float rb = __shfl_down_sync(FULL, vb, 1);

        fn2 = fmaf(f, f, fn2);
        dot[0] = fmaf(lt, f, dot[0]); pn2[0] = fmaf(lt, lt, pn2[0]);
        dot[1] = fmaf(vt, f, dot[1]); pn2[1] = fmaf(vt, vt, pn2[1]);
        dot[2] = fmaf(rt, f, dot[2]); pn2[2] = fmaf(rt, rt, pn2[2]);
        dot[3] = fmaf(lm, f, dot[3]); pn2[3] = fmaf(lm, lm, pn2[3]);
        dot[4] = fmaf(vm, f, dot[4]); pn2[4] = fmaf(vm, vm, pn2[4]);
        dot[5] = fmaf(rm, f, dot[5]); pn2[5] = fmaf(rm, rm, pn2[5]);
        dot[6] = fmaf(lb, f, dot[6]); pn2[6] = fmaf(lb, lb, pn2[6]);
        dot[7] = fmaf(vb, f, dot[7]); pn2[7] = fmaf(vb, vb, pn2[7]);
        dot[8] = fmaf(rb, f, dot[8]); pn2[8] = fmaf(rb, rb, pn2[8]);
    }

    // ---- weights: 0.5*softmax(cos) + 0.5*softmax(-dist) ----
    float fn = fmaxf(sqrtf(fn2), EPSF);
    float cs[KP], ed[KP];
    float cmax = -1e30f, emax = -1e30f;
#pragma unroll
    for (int k = 0; k < KP; k++) {
        float pn = fmaxf(sqrtf(pn2[k]), EPSF);
        float cv = dot[k] / (pn * fn);
        float d2 = pn2[k] + fn2 - 2.0f * dot[k];
        float ev = -sqrtf(fmaxf(d2, 0.0f));
        cs[k] = cv; ed[k] = ev;
        cmax = fmaxf(cmax, cv);
        emax = fmaxf(emax, ev);
    }
    float csum = 0.0f, esum = 0.0f;
#pragma unroll
    for (int k = 0; k < KP; k++) {
        cs[k] = __expf(cs[k] - cmax); csum += cs[k];
        ed[k] = __expf(ed[k] - emax); esum += ed[k];
    }
    float ci = 0.5f / csum, ei = 0.5f / esum;
    float wgt[KP];
#pragma unroll
    for (int k = 0; k < KP; k++) wgt[k] = cs[k] * ci + ed[k] * ei;

    // ---- pass 2: refined = sum_k w_k p_k ; out = refined + fe ----
    const bool wok = (lane >= 1) && (lane <= SEGW) && (gx < WW);
    float* outp = out + (((size_t)b * CC) * HH + h) * WW + gxc;

#pragma unroll 4
    for (int c = 0; c < CC; c++) {
        const float* p = fup + (size_t)c * HW;
        float vt = (xok && y0) ? p[-WW] : 0.0f;
        float vm =  xok        ? p[0]   : 0.0f;
        float vb = (xok && y2) ? p[WW]  : 0.0f;
        float f  =  xok        ? fep[(size_t)c * HW] : 0.0f;

        float lt = __shfl_up_sync(FULL, vt, 1);
        float rt = __shfl_down_sync(FULL, vt, 1);
        float lm = __shfl_up_sync(FULL, vm, 1);
        float rm = __shfl_down_sync(FULL, vm, 1);
        float lb = __shfl_up_sync(FULL, vb, 1);
        float rb = __shfl_down_sync(FULL, vb, 1);

        float r = lt * wgt[0];
        r = fmaf(vt, wgt[1], r);
        r = fmaf(rt, wgt[2], r);
        r = fmaf(lm, wgt[3], r);
        r = fmaf(vm, wgt[4], r);
        r = fmaf(rm, wgt[5], r);
        r = fmaf(lb, wgt[6], r);
        r = fmaf(vb, wgt[7], r);
        r = fmaf(rb, wgt[8], r);
        if (wok) outp[(size_t)c * HW] = r + f;
    }
}

extern "C" void kernel_launch(void* const* d_in, const int* in_sizes, int n_in,
                              void* d_out, int out_size)
{
    (void)in_sizes; (void)n_in; (void)out_size;
    const float* fe = (const float*)d_in[0];
    const float* fu = (const float*)d_in[1];
    float* out = (float*)d_out;

    dim3 grid(NSEG, HH / WPB, 4);
    asfr_kernel<<<grid, NT>>>(fe, fu, out);
}

// round 6
// speedup vs baseline: 2.7068x; 1.0711x over previous
#include <cuda_runtime.h>
#include <math.h>

#define CC 32
#define HH 256
#define WW 256
#define KP 9
#define EPSF 1e-12f
#define SEGW 30                // output pixels per warp
#define NSEG ((WW + SEGW - 1) / SEGW)   // 9
#define WPB 8                  // warps per block
#define NT (WPB * 32)
#define HW (HH * WW)

__global__ __launch_bounds__(NT) void asfr_kernel(
    const float* __restrict__ fe,
    const float* __restrict__ fu,
    float* __restrict__ out)
{
    const unsigned FULL = 0xffffffffu;
    const int lane = threadIdx.x & 31;
    const int wid  = threadIdx.x >> 5;
    const int seg  = blockIdx.x;
    const int h    = blockIdx.y * WPB + wid;
    const int b    = blockIdx.z;

    const int gx   = seg * SEGW - 1 + lane;          // [-1 .. 270]
    const bool xok = (gx >= 0) && (gx < WW);
    const bool y0  = (h > 0);
    const bool y2  = (h < HH - 1);
    const int gxc  = min(max(gx, 0), WW - 1);        // safe address

    const float* fup = fu + (((size_t)b * CC) * HH + h) * WW + gxc;
    const float* fep = fe + (((size_t)b * CC) * HH + h) * WW + gxc;

    // ---- pass 1: per-lane accumulators; redistribute via shuffle at end ----
    // u_dy = sum_c v(x,dy)*f(x+1)  -> dot[dx=-1] of lane x+1
    // m_dy = sum_c v(x,dy)*f(x)    -> dot[dx=0]
    // w_dy = sum_c v(x,dy)*f(x-1)  -> dot[dx=+1] of lane x-1
    // q_dy = sum_c v(x,dy)^2       -> pn2 of column x (all dx offsets)
    float u0 = 0, u1 = 0, u2 = 0;
    float m0 = 0, m1 = 0, m2 = 0;
    float w0 = 0, w1 = 0, w2 = 0;
    float q0 = 0, q1 = 0, q2 = 0;
    float fn2 = 0;

#pragma unroll 4
    for (int c = 0; c < CC; c++) {
        const float* p = fup + (size_t)c * HW;
        float vt = (xok && y0) ? p[-WW] : 0.0f;
        float vm =  xok        ? p[0]   : 0.0f;
        float vb = (xok && y2) ? p[WW]  : 0.0f;
        float f  =  xok        ? fep[(size_t)c * HW] : 0.0f;

        float fl = __shfl_up_sync(FULL, f, 1);
        float fr = __shfl_down_sync(FULL, f, 1);

        fn2 = fmaf(f, f, fn2);
        u0 = fmaf(vt, fr, u0); u1 = fmaf(vm, fr, u1); u2 = fmaf(vb, fr, u2);
        m0 = fmaf(vt, f,  m0); m1 = fmaf(vm, f,  m1); m2 = fmaf(vb, f,  m2);
        w0 = fmaf(vt, fl, w0); w1 = fmaf(vm, fl, w1); w2 = fmaf(vb, fl, w2);
        q0 = fmaf(vt, vt, q0); q1 = fmaf(vm, vm, q1); q2 = fmaf(vb, vb, q2);
    }

    // redistribute: k = dy*3 + dx + 1
    float dot[KP], pn2[KP];
    dot[0] = __shfl_up_sync(FULL, u0, 1);
    dot[3] = __shfl_up_sync(FULL, u1, 1);
    dot[6] = __shfl_up_sync(FULL, u2, 1);
    dot[1] = m0; dot[4] = m1; dot[7] = m2;
    dot[2] = __shfl_down_sync(FULL, w0, 1);
    dot[5] = __shfl_down_sync(FULL, w1, 1);
    dot[8] = __shfl_down_sync(FULL, w2, 1);
    pn2[0] = __shfl_up_sync(FULL, q0, 1);
    pn2[3] = __shfl_up_sync(FULL, q1, 1);
    pn2[6] = __shfl_up_sync(FULL, q2, 1);
    pn2[1] = q0; pn2[4] = q1; pn2[7] = q2;
    pn2[2] = __shfl_down_sync(FULL, q0, 1);
    pn2[5] = __shfl_down_sync(FULL, q1, 1);
    pn2[8] = __shfl_down_sync(FULL, q2, 1);

    // ---- weights: 0.5*softmax(cos) + 0.5*softmax(-dist) ----
    float fn = fmaxf(sqrtf(fn2), EPSF);
    float cs[KP], ed[KP];
    float cmax = -1e30f, emax = -1e30f;
#pragma unroll
    for (int k = 0; k < KP; k++) {
        float pn = fmaxf(sqrtf(pn2[k]), EPSF);
        float cv = dot[k] / (pn * fn);
        float d2 = pn2[k] + fn2 - 2.0f * dot[k];
        float ev = -sqrtf(fmaxf(d2, 0.0f));
        cs[k] = cv; ed[k] = ev;
        cmax = fmaxf(cmax, cv);
        emax = fmaxf(emax, ev);
    }
    float csum = 0.0f, esum = 0.0f;
#pragma unroll
    for (int k = 0; k < KP; k++) {
        cs[k] = __expf(cs[k] - cmax); csum += cs[k];
        ed[k] = __expf(ed[k] - emax); esum += ed[k];
    }
    float ci = 0.5f / csum, ei = 0.5f / esum;
    float wgt[KP];
#pragma unroll
    for (int k = 0; k < KP; k++) wgt[k] = cs[k] * ci + ed[k] * ei;

    // pre-shuffled neighbor weights (once):
    // wl_dy = wgt_{x-1}(dx=+1,dy)  (k = 2,5,8 shuffled up)
    // wr_dy = wgt_{x+1}(dx=-1,dy)  (k = 0,3,6 shuffled down)
    float wl0 = __shfl_up_sync(FULL, wgt[2], 1);
    float wl1 = __shfl_up_sync(FULL, wgt[5], 1);
    float wl2 = __shfl_up_sync(FULL, wgt[8], 1);
    float wr0 = __shfl_down_sync(FULL, wgt[0], 1);
    float wr1 = __shfl_down_sync(FULL, wgt[3], 1);
    float wr2 = __shfl_down_sync(FULL, wgt[6], 1);

    // ---- pass 2: scatter-style weighted sum ----
    const bool wok = (lane >= 1) && (lane <= SEGW) && (gx < WW);
    float* outp = out + (((size_t)b * CC) * HH + h) * WW + gxc;

#pragma unroll 4
    for (int c = 0; c < CC; c++) {
        const float* p = fup + (size_t)c * HW;
        float vt = (xok && y0) ? p[-WW] : 0.0f;
        float vm =  xok        ? p[0]   : 0.0f;
        float vb = (xok && y2) ? p[WW]  : 0.0f;
        float f  =  xok        ? fep[(size_t)c * HW] : 0.0f;

        float o  = vt * wgt[1];
        o = fmaf(vm, wgt[4], o);
        o = fmaf(vb, wgt[7], o);
        float cl = vt * wl0;            // contribution to output x-1
        cl = fmaf(vm, wl1, cl);
        cl = fmaf(vb, wl2, cl);
        float cr = vt * wr0;            // contribution to output x+1
        cr = fmaf(vm, wr1, cr);
        cr = fmaf(vb, wr2, cr);

        float from_right = __shfl_down_sync(FULL, cl, 1);
        float from_left  = __shfl_up_sync(FULL, cr, 1);
        float r = o + from_right + from_left;
        if (wok) outp[(size_t)c * HW] = r + f;
    }
}

extern "C" void kernel_launch(void* const* d_in, const int* in_sizes, int n_in,
                              void* d_out, int out_size)
{
    (void)in_sizes; (void)n_in; (void)out_size;
    const float* fe = (const float*)d_in[0];
    const float* fu = (const float*)d_in[1];
    float* out = (float*)d_out;

    dim3 grid(NSEG, HH / WPB, 4);
    asfr_kernel<<<grid, NT>>>(fe, fu, out);
}

// round 7
// speedup vs baseline: 3.2427x; 1.1980x over previous
#include <cuda_runtime.h>
#include <math.h>

#define CC 32
#define HH 256
#define WW 256
#define KP 9
#define EPSF 1e-12f
#define SEGO 62                 // output pixels per warp
#define NSEG 5                  // ceil(256/62)
#define WPB 4                   // warps per block
#define NT (WPB * 32)
#define HW (HH * WW)

__device__ __forceinline__ float2 ld2(const float* p) {
    return *reinterpret_cast<const float2*>(p);
}

__device__ __forceinline__ void weights9(const float* __restrict__ dot,
                                         const float* __restrict__ pn2,
                                         float fn2,
                                         float* __restrict__ wgt)
{
    float fn = fmaxf(sqrtf(fn2), EPSF);
    float cs[KP], ed[KP];
    float cmax = -1e30f, emax = -1e30f;
#pragma unroll
    for (int k = 0; k < KP; k++) {
        float pn = fmaxf(sqrtf(pn2[k]), EPSF);
        float cv = dot[k] / (pn * fn);
        float d2 = pn2[k] + fn2 - 2.0f * dot[k];
        float ev = -sqrtf(fmaxf(d2, 0.0f));
        cs[k] = cv; ed[k] = ev;
        cmax = fmaxf(cmax, cv);
        emax = fmaxf(emax, ev);
    }
    float csum = 0.0f, esum = 0.0f;
#pragma unroll
    for (int k = 0; k < KP; k++) {
        cs[k] = __expf(cs[k] - cmax); csum += cs[k];
        ed[k] = __expf(ed[k] - emax); esum += ed[k];
    }
    float ci = 0.5f / csum, ei = 0.5f / esum;
#pragma unroll
    for (int k = 0; k < KP; k++) wgt[k] = cs[k] * ci + ed[k] * ei;
}

template<bool XE>
__device__ __forceinline__ void body(
    int lane, int seg, int h, int b,
    const float* __restrict__ fe,
    const float* __restrict__ fu,
    float* __restrict__ out)
{
    const unsigned FULL = 0xffffffffu;
    const int w0 = seg * SEGO - 2;
    const int c0 = w0 + 2 * lane;       // even
    const int c1 = c0 + 1;
    const int ca = min(max(c0, 0), WW - 2);   // clamped even address col

    float mx0 = 1.0f, mx1 = 1.0f;
    if (XE) {
        mx0 = (c0 >= 0 && c0 < WW) ? 1.0f : 0.0f;
        mx1 = (c1 >= 0 && c1 < WW) ? 1.0f : 0.0f;
    }

    const bool y0 = (h > 0);
    const bool y2 = (h < HH - 1);

    const size_t rowoff = (((size_t)b * CC) * HH + h) * WW;
    const float* fup = fu + rowoff + ca;
    const float* fep = fe + rowoff + ca;

    // ---- pass 1: per-column scatter accumulators ----
    // per column (A = c0, B = c1), per dy in {t,m,b}:
    //   u = sum_c v * f(col+1) ; m = sum_c v * f(col) ;
    //   w = sum_c v * f(col-1) ; q = sum_c v^2
    float uA[3] = {0,0,0}, mA[3] = {0,0,0}, wA[3] = {0,0,0}, qA[3] = {0,0,0};
    float uB[3] = {0,0,0}, mB[3] = {0,0,0}, wB[3] = {0,0,0}, qB[3] = {0,0,0};
    float fnA = 0.0f, fnB = 0.0f;

#pragma unroll 4
    for (int c = 0; c < CC; c++) {
        const float* p = fup + c * HW;
        float2 vt = make_float2(0.0f, 0.0f);
        float2 vb = make_float2(0.0f, 0.0f);
        if (y0) vt = ld2(p - WW);
        float2 vm = ld2(p);
        if (y2) vb = ld2(p + WW);
        float2 f  = ld2(fep + c * HW);
        if (XE) {
            vt.x *= mx0; vt.y *= mx1;
            vm.x *= mx0; vm.y *= mx1;
            vb.x *= mx0; vb.y *= mx1;
        }

        float fl = __shfl_up_sync(FULL, f.y, 1);    // f(c0-1)
        float fr = __shfl_down_sync(FULL, f.x, 1);  // f(c1+1)

        fnA = fmaf(f.x, f.x, fnA);
        fnB = fmaf(f.y, f.y, fnB);

        float vx, vy;
        vx = vt.x; vy = vt.y;
        uA[0] = fmaf(vx, f.y, uA[0]); mA[0] = fmaf(vx, f.x, mA[0]);
        wA[0] = fmaf(vx, fl,  wA[0]); qA[0] = fmaf(vx, vx,  qA[0]);
        uB[0] = fmaf(vy, fr,  uB[0]); mB[0] = fmaf(vy, f.y, mB[0]);
        wB[0] = fmaf(vy, f.x, wB[0]); qB[0] = fmaf(vy, vy,  qB[0]);
        vx = vm.x; vy = vm.y;
        uA[1] = fmaf(vx, f.y, uA[1]); mA[1] = fmaf(vx, f.x, mA[1]);
        wA[1] = fmaf(vx, fl,  wA[1]); qA[1] = fmaf(vx, vx,  qA[1]);
        uB[1] = fmaf(vy, fr,  uB[1]); mB[1] = fmaf(vy, f.y, mB[1]);
        wB[1] = fmaf(vy, f.x, wB[1]); qB[1] = fmaf(vy, vy,  qB[1]);
        vx = vb.x; vy = vb.y;
        uA[2] = fmaf(vx, f.y, uA[2]); mA[2] = fmaf(vx, f.x, mA[2]);
        wA[2] = fmaf(vx, fl,  wA[2]); qA[2] = fmaf(vx, vx,  qA[2]);
        uB[2] = fmaf(vy, fr,  uB[2]); mB[2] = fmaf(vy, f.y, mB[2]);
        wB[2] = fmaf(vy, f.x, wB[2]); qB[2] = fmaf(vy, vy,  qB[2]);
    }

    // ---- redistribute + softmax, px A (col c0) ----
    // k = dy*3 + dx + 1 ; dx=-1 <- u(col-1), dx=0 <- m(col), dx=+1 <- w(col+1)
    float wgtA[KP], wgtB[KP];
    {
        float dot[KP], pn2[KP];
#pragma unroll
        for (int d = 0; d < 3; d++) {
            dot[d*3 + 0] = __shfl_up_sync(FULL, uB[d], 1);   // u(c0-1) = left lane uB
            dot[d*3 + 1] = mA[d];
            dot[d*3 + 2] = wB[d];                            // w(c0+1) = own B
            pn2[d*3 + 0] = __shfl_up_sync(FULL, qB[d], 1);
            pn2[d*3 + 1] = qA[d];
            pn2[d*3 + 2] = qB[d];
        }
        weights9(dot, pn2, fnA, wgtA);
    }
    // ---- px B (col c1) ----
    {
        float dot[KP], pn2[KP];
#pragma unroll
        for (int d = 0; d < 3; d++) {
            dot[d*3 + 0] = uA[d];                            // u(c1-1) = own A
            dot[d*3 + 1] = mB[d];
            dot[d*3 + 2] = __shfl_down_sync(FULL, wA[d], 1); // w(c1+1) = right lane wA
            pn2[d*3 + 0] = qA[d];
            pn2[d*3 + 1] = qB[d];
            pn2[d*3 + 2] = __shfl_down_sync(FULL, qA[d], 1);
        }
        weights9(dot, pn2, fnB, wgtB);
    }

    // pre-shuffled neighbor weights:
    // column c0 -> output c0-1 (left lane's B) uses left lane's wgtB[2,5,8]
    // column c1 -> output c1+1 (right lane's A) uses right lane's wgtA[0,3,6]
    float wlB0 = __shfl_up_sync(FULL, wgtB[2], 1);
    float wlB1 = __shfl_up_sync(FULL, wgtB[5], 1);
    float wlB2 = __shfl_up_sync(FULL, wgtB[8], 1);
    float wrA0 = __shfl_down_sync(FULL, wgtA[0], 1);
    float wrA1 = __shfl_down_sync(FULL, wgtA[3], 1);
    float wrA2 = __shfl_down_sync(FULL, wgtA[6], 1);

    // store validity
    const bool st0 = (lane >= 1) && (c0 >= 0) && (c0 < WW);
    const bool st1 = (lane <= 30) && (c1 >= 0) && (c1 < WW);
    float* ob = out + rowoff + ca;

    // ---- pass 2 ----
#pragma unroll 4
    for (int c = 0; c < CC; c++) {
        const float* p = fup + c * HW;
        float2 vt = make_float2(0.0f, 0.0f);
        float2 vb = make_float2(0.0f, 0.0f);
        if (y0) vt = ld2(p - WW);
        float2 vm = ld2(p);
        if (y2) vb = ld2(p + WW);
        float2 f  = ld2(fep + c * HW);
        if (XE) {
            vt.x *= mx0; vt.y *= mx1;
            vm.x *= mx0; vm.y *= mx1;
            vb.x *= mx0; vb.y *= mx1;
        }

        // output A (col c0): own col dx=0 (wgtA[1,4,7]) + col c1 as dx=+1 (wgtA[2,5,8])
        float accA = vt.x * wgtA[1];
        accA = fmaf(vm.x, wgtA[4], accA);
        accA = fmaf(vb.x, wgtA[7], accA);
        accA = fmaf(vt.y, wgtA[2], accA);
        accA = fmaf(vm.y, wgtA[5], accA);
        accA = fmaf(vb.y, wgtA[8], accA);
        // output B (col c1): own col dx=0 (wgtB[1,4,7]) + col c0 as dx=-1 (wgtB[0,3,6])
        float accB = vt.y * wgtB[1];
        accB = fmaf(vm.y, wgtB[4], accB);
        accB = fmaf(vb.y, wgtB[7], accB);
        accB = fmaf(vt.x, wgtB[0], accB);
        accB = fmaf(vm.x, wgtB[3], accB);
        accB = fmaf(vb.x, wgtB[6], accB);
        // cross-lane contributions
        float cl = vt.x * wlB0;          // col c0 -> left lane's output B
        cl = fmaf(vm.x, wlB1, cl);
        cl = fmaf(vb.x, wlB2, cl);
        float cr = vt.y * wrA0;          // col c1 -> right lane's output A
        cr = fmaf(vm.y, wrA1, cr);
        cr = fmaf(vb.y, wrA2, cr);

        float fromR = __shfl_down_sync(FULL, cl, 1);  // into own B
        float fromL = __shfl_up_sync(FULL, cr, 1);    // into own A

        float oA = accA + fromL + f.x;
        float oB = accB + fromR + f.y;

        float* q = ob + c * HW;
        if (st0 && st1) {
            *reinterpret_cast<float2*>(q) = make_float2(oA, oB);
        } else {
            if (st0) q[0] = oA;
            if (st1) q[1] = oB;
        }
    }
}

__global__ __launch_bounds__(NT) void asfr_kernel(
    const float* __restrict__ fe,
    const float* __restrict__ fu,
    float* __restrict__ out)
{
    const int lane = threadIdx.x & 31;
    const int wid  = threadIdx.x >> 5;
    const int seg  = blockIdx.x;
    const int h    = blockIdx.y * WPB + wid;
    const int b    = blockIdx.z;

    if (seg == 0 || seg == NSEG - 1)
        body<true>(lane, seg, h, b, fe, fu, out);
    else
        body<false>(lane, seg, h, b, fe, fu, out);
}

extern "C" void kernel_launch(void* const* d_in, const int* in_sizes, int n_in,
                              void* d_out, int out_size)
{
    (void)in_sizes; (void)n_in; (void)out_size;
    const float* fe = (const float*)d_in[0];
    const float* fu = (const float*)d_in[1];
    float* out = (float*)d_out;

    dim3 grid(NSEG, HH / WPB, 4);
    asfr_kernel<<<grid, NT>>>(fe, fu, out);
}